// round 7
// baseline (speedup 1.0000x reference)
#include <cuda_runtime.h>
#include <cstdint>

// BoundarySeg: out[b,j,0:768]   = sum_{d=0..5} w[b,j,d] * hidden[b, min(j+d,L-1), :]
//              out[b,j,768:1536]= hidden[b,j,:] * sum_d w[b,j,d]
// w[b,j,d] = span_adjacency[b, j, j+d] if j+d < L else 0.
// B=16, L=1024, H=768. fp32.
//
// R7: attack MIO store-issue cost. STG.128 costs 12cyc MIO issue; STS.128
// costs 4. Output goes STS -> double-buffered 12KB (2-j) smem chunks ->
// cp.async.bulk smem->gmem (engine-driven, no per-128B MIO issue).
// Input: direct LDG sliding register window (no TMA-in buffer, no mbarrier).
// smem = 24.8KB -> 6 CTAs/SM, 1 CTA barrier per j, drains pipelined with
// wait_group.read 1.

#define BB 16
#define LL 1024
#define HH 768
#define HV (HH / 4)            // 192 float4 per row
#define TJ 8                   // j's per CTA
#define CJ 2                   // j's per output chunk
#define NCHUNK (TJ / CJ)       // 4 chunks
#define SPAN 6
#define CHUNK_BYTES (CJ * 2 * HH * 4)    // 12288

struct __align__(16) SmemLayout {
    float4 ob[2][CJ * 2 * HV];   // 2 x 12288 B
    float  w[TJ * SPAN];         // 192 B
};

__device__ __forceinline__ uint32_t smem_u32(const void* p) {
    uint32_t a;
    asm("{ .reg .u64 t; cvta.to.shared.u64 t, %1; cvt.u32.u64 %0, t; }"
        : "=r"(a) : "l"(p));
    return a;
}

__global__ __launch_bounds__(HV, 6)
void boundary_seg_kernel(const float* __restrict__ adj,
                         const float* __restrict__ hid,
                         float* __restrict__ out)
{
    extern __shared__ __align__(16) char smem_raw[];
    SmemLayout* sm = reinterpret_cast<SmemLayout*>(smem_raw);

    const int tile = blockIdx.x;           // b * 128 + jt
    const int b  = tile >> 7;
    const int j0 = (tile & 127) * TJ;
    const int t  = threadIdx.x;            // float4 column of H

    const float4* __restrict__ hid4 =
        reinterpret_cast<const float4*>(hid) + (size_t)b * LL * HV;

    // Weights: 48 scattered L2 loads by the first 48 threads.
    if (t < TJ * SPAN) {
        const int jj = t / SPAN;
        const int d  = t - jj * SPAN;
        const int col = j0 + jj + d;
        float w = 0.0f;
        if (col < LL)
            w = __ldg(adj + ((size_t)b * LL + (j0 + jj)) * LL + col);
        sm->w[jj * SPAN + d] = w;
    }

    // Sliding register window of 6 hidden rows (direct LDG, L2-resident).
    float4 v[SPAN];
#pragma unroll
    for (int d = 0; d < SPAN; d++) {
        int r = j0 + d; if (r > LL - 1) r = LL - 1;
        v[d] = hid4[(size_t)r * HV + t];
    }

    __syncthreads();   // weights visible

#pragma unroll
    for (int c = 0; c < NCHUNK; c++) {
        const int buf = c & 1;
        float4* __restrict__ ob = sm->ob[buf];

        // Before refilling this buffer, make sure the bulk store issued
        // two chunks ago has finished reading it.
        if (c >= 2) {
            if (t == 0)
                asm volatile("cp.async.bulk.wait_group.read 1;" ::: "memory");
            __syncthreads();
        }

#pragma unroll
        for (int e = 0; e < CJ; e++) {
            const int jj = c * CJ + e;
            const int j  = j0 + jj;

            const float w0 = sm->w[jj * SPAN + 0], w1 = sm->w[jj * SPAN + 1];
            const float w2 = sm->w[jj * SPAN + 2], w3 = sm->w[jj * SPAN + 3];
            const float w4 = sm->w[jj * SPAN + 4], w5 = sm->w[jj * SPAN + 5];
            const float wsum = ((w0 + w1) + (w2 + w3)) + (w4 + w5);

            // Prefetch next window row early (independent of the FMA chain).
            int rn = j + SPAN; if (rn > LL - 1) rn = LL - 1;
            const float4 vnext = hid4[(size_t)rn * HV + t];

            float4 f;
            f.x = w0 * v[0].x; f.y = w0 * v[0].y;
            f.z = w0 * v[0].z; f.w = w0 * v[0].w;
            f.x = fmaf(w1, v[1].x, f.x); f.y = fmaf(w1, v[1].y, f.y);
            f.z = fmaf(w1, v[1].z, f.z); f.w = fmaf(w1, v[1].w, f.w);
            f.x = fmaf(w2, v[2].x, f.x); f.y = fmaf(w2, v[2].y, f.y);
            f.z = fmaf(w2, v[2].z, f.z); f.w = fmaf(w2, v[2].w, f.w);
            f.x = fmaf(w3, v[3].x, f.x); f.y = fmaf(w3, v[3].y, f.y);
            f.z = fmaf(w3, v[3].z, f.z); f.w = fmaf(w3, v[3].w, f.w);
            f.x = fmaf(w4, v[4].x, f.x); f.y = fmaf(w4, v[4].y, f.y);
            f.z = fmaf(w4, v[4].z, f.z); f.w = fmaf(w4, v[4].w, f.w);
            f.x = fmaf(w5, v[5].x, f.x); f.y = fmaf(w5, v[5].y, f.y);
            f.z = fmaf(w5, v[5].z, f.z); f.w = fmaf(w5, v[5].w, f.w);

            float4 s;
            s.x = v[0].x * wsum; s.y = v[0].y * wsum;
            s.z = v[0].z * wsum; s.w = v[0].w * wsum;

            ob[e * (2 * HV) + t]      = f;   // STS.128 (4cyc MIO)
            ob[e * (2 * HV) + HV + t] = s;

            // Slide the window.
#pragma unroll
            for (int d = 0; d < SPAN - 1; d++) v[d] = v[d + 1];
            v[SPAN - 1] = vnext;
        }

        __syncthreads();   // chunk staged

        if (t == 0) {
            asm volatile("fence.proxy.async.shared::cta;" ::: "memory");
            float* dst = out + ((size_t)b * LL + (j0 + c * CJ)) * (size_t)(2 * HH);
            asm volatile(
                "cp.async.bulk.global.shared::cta.bulk_group [%0], [%1], %2;"
                :: "l"(dst), "r"(smem_u32(ob)), "n"(CHUNK_BYTES) : "memory");
            asm volatile("cp.async.bulk.commit_group;" ::: "memory");
        }
    }

    // Full completion of all outstanding bulk stores before CTA exit.
    if (t == 0)
        asm volatile("cp.async.bulk.wait_group 0;" ::: "memory");
}

extern "C" void kernel_launch(void* const* d_in, const int* in_sizes, int n_in,
                              void* d_out, int out_size)
{
    const float* adj = (const float*)d_in[0];   // (B,L,L,1)
    const float* hid = (const float*)d_in[1];   // (B,L,H)
    float* out = (float*)d_out;                 // (B,L,2H)

    const int smem_bytes = (int)sizeof(SmemLayout);
    static bool attr_set = false;
    if (!attr_set) {
        cudaFuncSetAttribute(boundary_seg_kernel,
                             cudaFuncAttributeMaxDynamicSharedMemorySize,
                             smem_bytes);
        attr_set = true;
    }

    const int grid = BB * (LL / TJ);            // 2048 CTAs
    boundary_seg_kernel<<<grid, HV, smem_bytes>>>(adj, hid, out);
}

// round 8
// speedup vs baseline: 1.0167x; 1.0167x over previous
#include <cuda_runtime.h>
#include <cstdint>

// BoundarySeg: out[b,j,0:768]   = sum_{d=0..5} w[b,j,d] * hidden[b, min(j+d,L-1), :]
//              out[b,j,768:1536]= hidden[b,j,:] * sum_d w[b,j,d]
// w[b,j,d] = span_adjacency[b, j, j+d] if j+d < L else 0.
// B=16, L=1024, H=768. fp32.
//
// R8: maximize memory-level parallelism. Each thread loads ALL 13 window
// rows (its float4 column) as independent LDG.128s issued back-to-back
// (MLP=13), then computes all 8 j's purely from registers and stores with
// streaming STG.128. No smem data staging, no TMA, one barrier (weights).
// L1tex traffic = 80MB in + 96MB out (vs 262MB with smem staging).

#define BB 16
#define LL 1024
#define HH 768
#define HV (HH / 4)            // 192 float4 per row
#define TJ 8                   // j's per CTA
#define SPAN 6
#define NROWS (TJ + SPAN - 1)  // 13 rows cached in registers

__device__ __forceinline__ void stcs4(float4* p, float4 v) {
    asm volatile("st.global.cs.v4.f32 [%0], {%1,%2,%3,%4};"
                 :: "l"(p), "f"(v.x), "f"(v.y), "f"(v.z), "f"(v.w) : "memory");
}

__global__ __launch_bounds__(HV)
void boundary_seg_kernel(const float* __restrict__ adj,
                         const float* __restrict__ hid,
                         float* __restrict__ out)
{
    __shared__ float wsm[TJ * SPAN];

    const int tile = blockIdx.x;           // b * 128 + jt
    const int b  = tile >> 7;
    const int j0 = (tile & 127) * TJ;
    const int t  = threadIdx.x;            // float4 column of H

    const float4* __restrict__ hid4 =
        reinterpret_cast<const float4*>(hid) + (size_t)b * LL * HV;

    // All 13 window rows, fully independent loads -> deep MLP.
    float4 v[NROWS];
#pragma unroll
    for (int d = 0; d < NROWS; d++) {
        int r = j0 + d; if (r > LL - 1) r = LL - 1;
        v[d] = __ldg(&hid4[(size_t)r * HV + t]);
    }

    // Weights: 48 scattered loads by the first 48 threads (overlaps the
    // row loads above — no dependence until the barrier).
    if (t < TJ * SPAN) {
        const int jj = t / SPAN;
        const int d  = t - jj * SPAN;
        const int col = j0 + jj + d;
        float w = 0.0f;
        if (col < LL)
            w = __ldg(adj + ((size_t)b * LL + (j0 + jj)) * LL + col);
        wsm[jj * SPAN + d] = w;
    }
    __syncthreads();

    float4* __restrict__ out4 = reinterpret_cast<float4*>(out);

#pragma unroll
    for (int jj = 0; jj < TJ; jj++) {
        const float w0 = wsm[jj * SPAN + 0], w1 = wsm[jj * SPAN + 1];
        const float w2 = wsm[jj * SPAN + 2], w3 = wsm[jj * SPAN + 3];
        const float w4 = wsm[jj * SPAN + 4], w5 = wsm[jj * SPAN + 5];
        const float wsum = ((w0 + w1) + (w2 + w3)) + (w4 + w5);

        float4 f;
        f.x = w0 * v[jj + 0].x; f.y = w0 * v[jj + 0].y;
        f.z = w0 * v[jj + 0].z; f.w = w0 * v[jj + 0].w;
        f.x = fmaf(w1, v[jj + 1].x, f.x); f.y = fmaf(w1, v[jj + 1].y, f.y);
        f.z = fmaf(w1, v[jj + 1].z, f.z); f.w = fmaf(w1, v[jj + 1].w, f.w);
        f.x = fmaf(w2, v[jj + 2].x, f.x); f.y = fmaf(w2, v[jj + 2].y, f.y);
        f.z = fmaf(w2, v[jj + 2].z, f.z); f.w = fmaf(w2, v[jj + 2].w, f.w);
        f.x = fmaf(w3, v[jj + 3].x, f.x); f.y = fmaf(w3, v[jj + 3].y, f.y);
        f.z = fmaf(w3, v[jj + 3].z, f.z); f.w = fmaf(w3, v[jj + 3].w, f.w);
        f.x = fmaf(w4, v[jj + 4].x, f.x); f.y = fmaf(w4, v[jj + 4].y, f.y);
        f.z = fmaf(w4, v[jj + 4].z, f.z); f.w = fmaf(w4, v[jj + 4].w, f.w);
        f.x = fmaf(w5, v[jj + 5].x, f.x); f.y = fmaf(w5, v[jj + 5].y, f.y);
        f.z = fmaf(w5, v[jj + 5].z, f.z); f.w = fmaf(w5, v[jj + 5].w, f.w);

        float4 s;
        s.x = v[jj].x * wsum; s.y = v[jj].y * wsum;
        s.z = v[jj].z * wsum; s.w = v[jj].w * wsum;

        const size_t obase = ((size_t)b * LL + (j0 + jj)) * (size_t)(2 * HV);
        stcs4(out4 + obase + t, f);
        stcs4(out4 + obase + HV + t, s);
    }
}

extern "C" void kernel_launch(void* const* d_in, const int* in_sizes, int n_in,
                              void* d_out, int out_size)
{
    const float* adj = (const float*)d_in[0];   // (B,L,L,1)
    const float* hid = (const float*)d_in[1];   // (B,L,H)
    float* out = (float*)d_out;                 // (B,L,2H)

    const int grid = BB * (LL / TJ);            // 2048 CTAs
    boundary_seg_kernel<<<grid, HV>>>(adj, hid, out);
}

// round 9
// speedup vs baseline: 1.0654x; 1.0479x over previous
#include <cuda_runtime.h>
#include <cstdint>

// BoundarySeg: out[b,j,0:768]   = sum_{d=0..5} w[b,j,d] * hidden[b, min(j+d,L-1), :]
//              out[b,j,768:1536]= hidden[b,j,:] * sum_d w[b,j,d]
// w[b,j,d] = span_adjacency[b, j, j+d] if j+d < L else 0.
// B=16, L=1024, H=768. fp32.
//
// R9: R2 skeleton (TMA bulk-in + LDS sliding window + direct STG out) with
// TJ=16 to cut L2 read bytes 20% (amplification 21/16 vs 13/8), and
// streaming .cs stores so the 96MB write stream evicts early instead of
// churning the L2-resident hidden tensor. Theory: LTS total throughput
// (reads+writes) is the binding resource.

#define BB 16
#define LL 1024
#define HH 768
#define HV (HH / 4)            // 192 float4 per row
#define TJ 16                  // j's per CTA
#define SPAN 6
#define NROWS (TJ + SPAN - 1)  // 21 rows staged

struct __align__(16) SmemLayout {
    float4   in[NROWS * HV];     // 64512 B
    float    w[TJ * SPAN];       // 384 B
    uint64_t mbar;
};

__device__ __forceinline__ uint32_t smem_u32(const void* p) {
    uint32_t a;
    asm("{ .reg .u64 t; cvta.to.shared.u64 t, %1; cvt.u32.u64 %0, t; }"
        : "=r"(a) : "l"(p));
    return a;
}

__device__ __forceinline__ void stcs4(float4* p, float4 v) {
    asm volatile("st.global.cs.v4.f32 [%0], {%1,%2,%3,%4};"
                 :: "l"(p), "f"(v.x), "f"(v.y), "f"(v.z), "f"(v.w) : "memory");
}

__global__ __launch_bounds__(HV)
void boundary_seg_kernel(const float* __restrict__ adj,
                         const float* __restrict__ hid,
                         float* __restrict__ out)
{
    extern __shared__ __align__(16) char smem_raw[];
    SmemLayout* sm = reinterpret_cast<SmemLayout*>(smem_raw);

    const int tile = blockIdx.x;           // b * 64 + jt
    const int b  = tile >> 6;
    const int j0 = (tile & 63) * TJ;
    const int t  = threadIdx.x;            // float4 column of H

    const int rl = min(NROWS, LL - j0);    // rows actually available
    const uint32_t in_bytes = (uint32_t)rl * HH * 4u;

    const uint32_t s_in   = smem_u32(sm->in);
    const uint32_t s_mbar = smem_u32(&sm->mbar);

    if (t == 0) {
        asm volatile("mbarrier.init.shared::cta.b64 [%0], %1;"
                     :: "r"(s_mbar), "r"(1) : "memory");
    }
    __syncthreads();

    if (t == 0) {
        asm volatile("mbarrier.arrive.expect_tx.shared::cta.b64 _, [%0], %1;"
                     :: "r"(s_mbar), "r"(in_bytes) : "memory");
        const float* src = hid + ((size_t)b * LL + j0) * HH;
        asm volatile(
            "cp.async.bulk.shared::cluster.global.mbarrier::complete_tx::bytes "
            "[%0], [%1], %2, [%3];"
            :: "r"(s_in), "l"(src), "r"(in_bytes), "r"(s_mbar) : "memory");
    }

    // Weights: 96 scattered L2 loads, overlapped with the TMA.
    if (t < TJ * SPAN) {
        const int jj = t / SPAN;
        const int d  = t - jj * SPAN;
        const int col = j0 + jj + d;
        float w = 0.0f;
        if (col < LL)
            w = __ldg(adj + ((size_t)b * LL + (j0 + jj)) * LL + col);
        sm->w[jj * SPAN + d] = w;
    }
    __syncthreads();

    // Wait for the TMA bulk copy.
    {
        uint32_t done;
        do {
            asm volatile(
                "{ .reg .pred p;\n\t"
                "  mbarrier.try_wait.parity.shared::cta.b64 p, [%1], %2, 10000000;\n\t"
                "  selp.b32 %0, 1, 0, p; }"
                : "=r"(done) : "r"(s_mbar), "r"(0u) : "memory");
        } while (!done);
    }

    const int rmax = rl - 1;

    // Sliding register window of 6 rows (this thread's float4 column).
    float4 v[SPAN];
#pragma unroll
    for (int d = 0; d < SPAN; d++)
        v[d] = sm->in[min(d, rmax) * HV + t];

    float4* __restrict__ out4 = reinterpret_cast<float4*>(out);

#pragma unroll
    for (int jj = 0; jj < TJ; jj++) {
        const float w0 = sm->w[jj * SPAN + 0], w1 = sm->w[jj * SPAN + 1];
        const float w2 = sm->w[jj * SPAN + 2], w3 = sm->w[jj * SPAN + 3];
        const float w4 = sm->w[jj * SPAN + 4], w5 = sm->w[jj * SPAN + 5];
        const float wsum = ((w0 + w1) + (w2 + w3)) + (w4 + w5);

        float4 f;
        f.x = w0 * v[0].x; f.y = w0 * v[0].y;
        f.z = w0 * v[0].z; f.w = w0 * v[0].w;
        f.x = fmaf(w1, v[1].x, f.x); f.y = fmaf(w1, v[1].y, f.y);
        f.z = fmaf(w1, v[1].z, f.z); f.w = fmaf(w1, v[1].w, f.w);
        f.x = fmaf(w2, v[2].x, f.x); f.y = fmaf(w2, v[2].y, f.y);
        f.z = fmaf(w2, v[2].z, f.z); f.w = fmaf(w2, v[2].w, f.w);
        f.x = fmaf(w3, v[3].x, f.x); f.y = fmaf(w3, v[3].y, f.y);
        f.z = fmaf(w3, v[3].z, f.z); f.w = fmaf(w3, v[3].w, f.w);
        f.x = fmaf(w4, v[4].x, f.x); f.y = fmaf(w4, v[4].y, f.y);
        f.z = fmaf(w4, v[4].z, f.z); f.w = fmaf(w4, v[4].w, f.w);
        f.x = fmaf(w5, v[5].x, f.x); f.y = fmaf(w5, v[5].y, f.y);
        f.z = fmaf(w5, v[5].z, f.z); f.w = fmaf(w5, v[5].w, f.w);

        float4 s;
        s.x = v[0].x * wsum; s.y = v[0].y * wsum;
        s.z = v[0].z * wsum; s.w = v[0].w * wsum;

        const size_t obase = ((size_t)b * LL + (j0 + jj)) * (size_t)(2 * HV);
        stcs4(out4 + obase + t, f);
        stcs4(out4 + obase + HV + t, s);

        // Slide the window.
#pragma unroll
        for (int d = 0; d < SPAN - 1; d++) v[d] = v[d + 1];
        v[SPAN - 1] = sm->in[min(jj + SPAN, rmax) * HV + t];
    }
}

extern "C" void kernel_launch(void* const* d_in, const int* in_sizes, int n_in,
                              void* d_out, int out_size)
{
    const float* adj = (const float*)d_in[0];   // (B,L,L,1)
    const float* hid = (const float*)d_in[1];   // (B,L,H)
    float* out = (float*)d_out;                 // (B,L,2H)

    const int smem_bytes = (int)sizeof(SmemLayout);
    static bool attr_set = false;
    if (!attr_set) {
        cudaFuncSetAttribute(boundary_seg_kernel,
                             cudaFuncAttributeMaxDynamicSharedMemorySize,
                             smem_bytes);
        attr_set = true;
    }

    const int grid = BB * (LL / TJ);            // 1024 CTAs
    boundary_seg_kernel<<<grid, HV, smem_bytes>>>(adj, hid, out);
}

// round 10
// speedup vs baseline: 1.0755x; 1.0094x over previous
#include <cuda_runtime.h>
#include <cstdint>

// BoundarySeg: out[b,j,0:768]   = sum_{d=0..5} w[b,j,d] * hidden[b, min(j+d,L-1), :]
//              out[b,j,768:1536]= hidden[b,j,:] * sum_d w[b,j,d]
// w[b,j,d] = span_adjacency[b, j, j+d] if j+d < L else 0.
// B=16, L=1024, H=768. fp32.
//
// R10: persistent CTAs + cross-tile double-buffered TMA pipeline.
// 304 CTAs (2 resident/SM, single wave). Each CTA grid-strides over the
// 2048 8-j tiles; while computing tile k from buffer s, the TMA-in and
// weight loads for its next tile stream into buffer s^1. After the
// prologue no cold TMA wait is exposed. Compute: smem sliding register
// window + streaming .cs STG.128 (best path from R2/R9).

#define BB 16
#define LL 1024
#define HH 768
#define HV (HH / 4)            // 192 float4 per row
#define TJ 8                   // j's per tile
#define SPAN 6
#define NROWS (TJ + SPAN - 1)  // 13 rows staged per tile
#define NTILES (BB * (LL / TJ))  // 2048
#define GRID 304               // persistent CTAs (2 per SM)

struct __align__(16) SmemLayout {
    float4   in[2][NROWS * HV];   // 2 x 39936 B
    float    w[2][TJ * SPAN];     // 2 x 192 B
    uint64_t mbar[2];
};

__device__ __forceinline__ uint32_t smem_u32(const void* p) {
    uint32_t a;
    asm("{ .reg .u64 t; cvta.to.shared.u64 t, %1; cvt.u32.u64 %0, t; }"
        : "=r"(a) : "l"(p));
    return a;
}

__device__ __forceinline__ void stcs4(float4* p, float4 v) {
    asm volatile("st.global.cs.v4.f32 [%0], {%1,%2,%3,%4};"
                 :: "l"(p), "f"(v.x), "f"(v.y), "f"(v.z), "f"(v.w) : "memory");
}

// Prefetch one tile into slot s: t0 issues the bulk copy, threads 0..47
// fetch the 48 weights.
__device__ __forceinline__ void prefetch_tile(SmemLayout* sm, int s, int tile,
                                              const float* __restrict__ adj,
                                              const float* __restrict__ hid,
                                              int t)
{
    const int b  = tile >> 7;
    const int j0 = (tile & 127) * TJ;

    if (t == 0) {
        const int rl = min(NROWS, LL - j0);
        const uint32_t nbytes = (uint32_t)rl * HH * 4u;
        const uint32_t s_mb = smem_u32(&sm->mbar[s]);
        asm volatile("mbarrier.arrive.expect_tx.shared::cta.b64 _, [%0], %1;"
                     :: "r"(s_mb), "r"(nbytes) : "memory");
        const float* src = hid + ((size_t)b * LL + j0) * HH;
        asm volatile(
            "cp.async.bulk.shared::cluster.global.mbarrier::complete_tx::bytes "
            "[%0], [%1], %2, [%3];"
            :: "r"(smem_u32(sm->in[s])), "l"(src), "r"(nbytes), "r"(s_mb)
            : "memory");
    }
    if (t < TJ * SPAN) {
        const int jj = t / SPAN;
        const int d  = t - jj * SPAN;
        const int col = j0 + jj + d;
        float w = 0.0f;
        if (col < LL)
            w = __ldg(adj + ((size_t)b * LL + (j0 + jj)) * LL + col);
        sm->w[s][jj * SPAN + d] = w;
    }
}

__global__ __launch_bounds__(HV, 2)
void boundary_seg_kernel(const float* __restrict__ adj,
                         const float* __restrict__ hid,
                         float* __restrict__ out)
{
    extern __shared__ __align__(16) char smem_raw[];
    SmemLayout* sm = reinterpret_cast<SmemLayout*>(smem_raw);

    const int t = threadIdx.x;

    if (t == 0) {
#pragma unroll
        for (int s = 0; s < 2; s++)
            asm volatile("mbarrier.init.shared::cta.b64 [%0], %1;"
                         :: "r"(smem_u32(&sm->mbar[s])), "r"(1) : "memory");
    }
    __syncthreads();

    float4* __restrict__ out4 = reinterpret_cast<float4*>(out);

    int ph0 = 0, ph1 = 0;      // mbarrier phase per slot
    int cur = 0;

    // Prologue: prefetch my first tile into slot 0.
    int tile = blockIdx.x;
    if (tile < NTILES)
        prefetch_tile(sm, 0, tile, adj, hid, t);

    for (; tile < NTILES; tile += GRID) {
        // Slot cur^1 was fully consumed one iteration ago (or is fresh).
        __syncthreads();

        const int nxt = tile + GRID;
        if (nxt < NTILES)
            prefetch_tile(sm, cur ^ 1, nxt, adj, hid, t);

        // Wait for this tile's bulk copy.
        {
            const uint32_t s_mb = smem_u32(&sm->mbar[cur]);
            const uint32_t par = (cur == 0) ? (uint32_t)ph0 : (uint32_t)ph1;
            uint32_t done;
            do {
                asm volatile(
                    "{ .reg .pred p;\n\t"
                    "  mbarrier.try_wait.parity.shared::cta.b64 p, [%1], %2, 10000000;\n\t"
                    "  selp.b32 %0, 1, 0, p; }"
                    : "=r"(done) : "r"(s_mb), "r"(par) : "memory");
            } while (!done);
            if (cur == 0) ph0 ^= 1; else ph1 ^= 1;
        }

        const int b    = tile >> 7;
        const int j0   = (tile & 127) * TJ;
        const int rl   = min(NROWS, LL - j0);
        const int rmax = rl - 1;

        const float4* __restrict__ buf = sm->in[cur];
        const float*  __restrict__ wk  = sm->w[cur];

        // Sliding register window of 6 rows (this thread's float4 column).
        float4 v[SPAN];
#pragma unroll
        for (int d = 0; d < SPAN; d++)
            v[d] = buf[min(d, rmax) * HV + t];

#pragma unroll
        for (int jj = 0; jj < TJ; jj++) {
            const float w0 = wk[jj * SPAN + 0], w1 = wk[jj * SPAN + 1];
            const float w2 = wk[jj * SPAN + 2], w3 = wk[jj * SPAN + 3];
            const float w4 = wk[jj * SPAN + 4], w5 = wk[jj * SPAN + 5];
            const float wsum = ((w0 + w1) + (w2 + w3)) + (w4 + w5);

            float4 f;
            f.x = w0 * v[0].x; f.y = w0 * v[0].y;
            f.z = w0 * v[0].z; f.w = w0 * v[0].w;
            f.x = fmaf(w1, v[1].x, f.x); f.y = fmaf(w1, v[1].y, f.y);
            f.z = fmaf(w1, v[1].z, f.z); f.w = fmaf(w1, v[1].w, f.w);
            f.x = fmaf(w2, v[2].x, f.x); f.y = fmaf(w2, v[2].y, f.y);
            f.z = fmaf(w2, v[2].z, f.z); f.w = fmaf(w2, v[2].w, f.w);
            f.x = fmaf(w3, v[3].x, f.x); f.y = fmaf(w3, v[3].y, f.y);
            f.z = fmaf(w3, v[3].z, f.z); f.w = fmaf(w3, v[3].w, f.w);
            f.x = fmaf(w4, v[4].x, f.x); f.y = fmaf(w4, v[4].y, f.y);
            f.z = fmaf(w4, v[4].z, f.z); f.w = fmaf(w4, v[4].w, f.w);
            f.x = fmaf(w5, v[5].x, f.x); f.y = fmaf(w5, v[5].y, f.y);
            f.z = fmaf(w5, v[5].z, f.z); f.w = fmaf(w5, v[5].w, f.w);

            float4 s;
            s.x = v[0].x * wsum; s.y = v[0].y * wsum;
            s.z = v[0].z * wsum; s.w = v[0].w * wsum;

            const size_t obase =
                ((size_t)b * LL + (j0 + jj)) * (size_t)(2 * HV);
            stcs4(out4 + obase + t, f);
            stcs4(out4 + obase + HV + t, s);

            // Slide the window.
#pragma unroll
            for (int d = 0; d < SPAN - 1; d++) v[d] = v[d + 1];
            v[SPAN - 1] = buf[min(jj + SPAN, rmax) * HV + t];
        }

        cur ^= 1;
    }
}

extern "C" void kernel_launch(void* const* d_in, const int* in_sizes, int n_in,
                              void* d_out, int out_size)
{
    const float* adj = (const float*)d_in[0];   // (B,L,L,1)
    const float* hid = (const float*)d_in[1];   // (B,L,H)
    float* out = (float*)d_out;                 // (B,L,2H)

    const int smem_bytes = (int)sizeof(SmemLayout);
    static bool attr_set = false;
    if (!attr_set) {
        cudaFuncSetAttribute(boundary_seg_kernel,
                             cudaFuncAttributeMaxDynamicSharedMemorySize,
                             smem_bytes);
        attr_set = true;
    }

    boundary_seg_kernel<<<GRID, HV, smem_bytes>>>(adj, hid, out);
}